// round 6
// baseline (speedup 1.0000x reference)
#include <cuda_runtime.h>
#include <cuda_bf16.h>
#include <math.h>

// Problem constants
#define VOCAB 32000
#define D_IN  512
#define D_H   1024
#define D_OUT 64
#define BB    64
#define SS    256
#define M_TOT (BB * SS)          // 16384 rows, m = s*64 + b
#define G3H   (3 * D_H)          // 3072
#define GRID  128                // persistent CTAs
#define THR   384                // threads in persistent kernel

// Scratch (device globals — no allocation allowed)
__device__ float g_gi[(size_t)M_TOT * G3H];   // [S][B][3H]  192 MB
__device__ float g_hs[(size_t)M_TOT * D_H];   // [S][B][H]    64 MB
__device__ float g_hzero[BB * D_H];           // stays zero (never written)

// Grid-barrier state (reset each launch by k_reset)
__device__ unsigned g_cnt;
__device__ volatile unsigned g_gen;

__global__ void k_reset() { g_cnt = 0; g_gen = 0; }

// ---- packed fp32x2 helpers (sm_103a FFMA2: PTX-only, exact fp32 per half) ----
__device__ __forceinline__ void fma2(unsigned long long& d,
                                     unsigned long long a,
                                     unsigned long long b) {
    asm("fma.rn.f32x2 %0, %1, %2, %0;" : "+l"(d) : "l"(a), "l"(b));
}
__device__ __forceinline__ unsigned long long pack_dup(float x) {
    unsigned long long r;
    asm("mov.b64 %0, {%1, %1};" : "=l"(r) : "f"(x));
    return r;
}
__device__ __forceinline__ float2 unpack2(unsigned long long v) {
    float2 f;
    asm("mov.b64 {%0, %1}, %2;" : "=f"(f.x), "=f"(f.y) : "l"(v));
    return f;
}

// ---------------------------------------------------------------------------
// Kernel A: fused embedding gather + input projection GEMM (f32x2 inner loop)
//   gi[m][n] = sum_k emb[tok(m)][k] * w_ih[n][k] + b_ih[n]
// ---------------------------------------------------------------------------
__global__ void k_embed_gi(const int* __restrict__ x,
                           const float* __restrict__ emb,
                           const float* __restrict__ w_ih,
                           const float* __restrict__ b_ih) {
    __shared__ __align__(16) float As[16][136];
    __shared__ __align__(16) float Ws[16][136];
    __shared__ int tok[128];

    const int m0 = blockIdx.y * 128;
    const int n0 = blockIdx.x * 128;
    const int tid = threadIdx.x;
    const int tx = tid & 15;
    const int ty = tid >> 4;

    if (tid < 128) {
        int m = m0 + tid;
        tok[tid] = x[(m & 63) * SS + (m >> 6)];
    }
    __syncthreads();

    unsigned long long acc2[8][4];
#pragma unroll
    for (int i = 0; i < 8; i++)
#pragma unroll
        for (int j = 0; j < 4; j++) acc2[i][j] = 0ull;

    for (int k0 = 0; k0 < D_IN; k0 += 16) {
#pragma unroll
        for (int i = tid; i < 2048; i += 256) {
            int mm = i >> 4, kk = i & 15;
            As[kk][mm] = emb[(size_t)tok[mm] * D_IN + k0 + kk];
        }
#pragma unroll
        for (int i = tid; i < 2048; i += 256) {
            int nn = i >> 4, kk = i & 15;
            Ws[kk][nn] = w_ih[(size_t)(n0 + nn) * D_IN + k0 + kk];
        }
        __syncthreads();

#pragma unroll
        for (int kk = 0; kk < 16; kk++) {
            float a[8];
            *(float4*)&a[0] = *(const float4*)&As[kk][ty * 8];
            *(float4*)&a[4] = *(const float4*)&As[kk][ty * 8 + 4];
            ulonglong2 w01 = *(const ulonglong2*)&Ws[kk][tx * 8];      // col pairs (0,1),(2,3)
            ulonglong2 w23 = *(const ulonglong2*)&Ws[kk][tx * 8 + 4];  // col pairs (4,5),(6,7)
#pragma unroll
            for (int i = 0; i < 8; i++) {
                unsigned long long ad = pack_dup(a[i]);
                fma2(acc2[i][0], ad, w01.x);
                fma2(acc2[i][1], ad, w01.y);
                fma2(acc2[i][2], ad, w23.x);
                fma2(acc2[i][3], ad, w23.y);
            }
        }
        __syncthreads();
    }

    float bias[8];
#pragma unroll
    for (int j = 0; j < 8; j++) bias[j] = b_ih[n0 + tx * 8 + j];

#pragma unroll
    for (int i = 0; i < 8; i++) {
        size_t row = (size_t)(m0 + ty * 8 + i) * G3H + n0 + tx * 8;
        float2 c0 = unpack2(acc2[i][0]);
        float2 c1 = unpack2(acc2[i][1]);
        float2 c2 = unpack2(acc2[i][2]);
        float2 c3 = unpack2(acc2[i][3]);
        float4 v0 = make_float4(c0.x + bias[0], c0.y + bias[1],
                                c1.x + bias[2], c1.y + bias[3]);
        float4 v1 = make_float4(c2.x + bias[4], c2.y + bias[5],
                                c3.x + bias[6], c3.y + bias[7]);
        *(float4*)&g_gi[row]     = v0;
        *(float4*)&g_gi[row + 4] = v1;
    }
}

// ---------------------------------------------------------------------------
// Kernel B: PERSISTENT GRU — all 256 steps in one kernel, f32x2 math.
//   128 CTAs x 384 threads. CTA bid owns j in [bid*8, bid*8+8): 24 w_hh rows
//   packed as 12 row-pairs of f32x2 in SMEM (96 KB, resident all sequence).
//   Thread map: b = tid&63, rg = tid>>6 (0..5): rows 4rg..4rg+3 = pairs 2rg,2rg+1.
//   h staged b-major in SMEM chunks of 128 k (double buffered), pad 132 for
//   conflict-free float4 reads. GEMM writes gh to SMEM; separate epilogue map
//   (64b x 8j over 512 items) applies gates. Grid barrier between steps.
// ---------------------------------------------------------------------------
__global__ void k_gru_persist(const float* __restrict__ w_hh,
                              const float* __restrict__ b_hh) {
    extern __shared__ float sm[];
    float* w2   = sm;                        // [12 pairs][1024 k][2]   96 KB
    float* h_s  = sm + 24576;                // [2 bufs][64 b][132]     66 KB
    float* gh_s = sm + 24576 + 2 * 8448;     // [24 rows][66]            6 KB

    const int tid = threadIdx.x;             // 384
    const int bid = blockIdx.x;              // 128
    const int j0  = bid * 8;
    const int b   = tid & 63;
    const int rg  = tid >> 6;                // 0..5
    const int p0  = rg * 2;                  // pairs p0, p0+1

    // One-time: pack w_hh slice into SMEM as row-pair f32x2.
    // Local row l = jj*3 + g  (jj 0..7, g 0..2); pair p = l>>1, slot = l&1.
    for (int idx = tid; idx < 24 * 1024; idx += THR) {
        int l = idx >> 10, k = idx & 1023;
        int g = l % 3, jj = l / 3;
        w2[(((l >> 1) * 1024) + k) * 2 + (l & 1)] =
            w_hh[(size_t)(g * D_H + j0 + jj) * D_H + k];
    }

    // Epilogue item constants (items: i = jj*64 + b, 512 total over 384 thr)
    const int e_n = (tid < 512 - THR) ? 2 : 1;
    int   e_b[2], e_j[2];
    float e_bhr[2], e_bhz[2], e_bhn[2];
#pragma unroll
    for (int t = 0; t < 2; t++) {
        int i = tid + t * THR;
        int valid = (i < 512);
        e_b[t] = i & 63;
        e_j[t] = valid ? (j0 + (i >> 6)) : j0;
        e_bhr[t] = b_hh[e_j[t]];
        e_bhz[t] = b_hh[D_H + e_j[t]];
        e_bhn[t] = b_hh[2 * D_H + e_j[t]];
    }
    __syncthreads();

    for (int s = 0; s < SS; s++) {
        const float* hp = (s == 0) ? g_hzero : (g_hs + (size_t)(s - 1) * BB * D_H);
        float* ho = g_hs + (size_t)s * BB * D_H;

        // Prefetch epilogue operands (hidden under the GEMM)
        float p_gir[2], p_giz[2], p_gin[2], p_hp[2];
#pragma unroll
        for (int t = 0; t < 2; t++) {
            if (t < e_n) {
                const float* gi = g_gi + ((size_t)s * BB + e_b[t]) * G3H;
                p_gir[t] = gi[e_j[t]];
                p_giz[t] = gi[D_H + e_j[t]];
                p_gin[t] = gi[2 * D_H + e_j[t]];
                p_hp[t]  = hp[(size_t)e_b[t] * D_H + e_j[t]];
            }
        }

        unsigned long long acc0 = 0ull, acc1 = 0ull;

        // Load chunk 0 (coalesced global, b-major smem)
        for (int idx = tid; idx < 2048; idx += THR) {
            int bl = idx >> 5, kq = idx & 31;
            float4 v = *(const float4*)&hp[(size_t)bl * D_H + kq * 4];
            *(float4*)&h_s[bl * 132 + kq * 4] = v;
        }
        __syncthreads();

        for (int c = 0; c < 8; c++) {
            const int buf = c & 1;
            if (c < 7) {  // prefetch next chunk into the other buffer
                float* hd = h_s + (buf ^ 1) * 8448;
                for (int idx = tid; idx < 2048; idx += THR) {
                    int bl = idx >> 5, kq = idx & 31;
                    float4 v = *(const float4*)&hp[(size_t)bl * D_H + (c + 1) * 128 + kq * 4];
                    *(float4*)&hd[bl * 132 + kq * 4] = v;
                }
            }
            const float* hb = h_s + buf * 8448 + b * 132;
            const float* wA = w2 + (p0 * 1024 + c * 128) * 2;
            const float* wB = w2 + ((p0 + 1) * 1024 + c * 128) * 2;
#pragma unroll 8
            for (int kk = 0; kk < 128; kk += 4) {
                float4 hv = *(const float4*)&hb[kk];
                unsigned long long h0 = pack_dup(hv.x), h1 = pack_dup(hv.y);
                unsigned long long h2 = pack_dup(hv.z), h3 = pack_dup(hv.w);
                ulonglong2 wa0 = *(const ulonglong2*)&wA[kk * 2];
                ulonglong2 wa1 = *(const ulonglong2*)&wA[kk * 2 + 4];
                ulonglong2 wb0 = *(const ulonglong2*)&wB[kk * 2];
                ulonglong2 wb1 = *(const ulonglong2*)&wB[kk * 2 + 4];
                fma2(acc0, h0, wa0.x); fma2(acc0, h1, wa0.y);
                fma2(acc0, h2, wa1.x); fma2(acc0, h3, wa1.y);
                fma2(acc1, h0, wb0.x); fma2(acc1, h1, wb0.y);
                fma2(acc1, h2, wb1.x); fma2(acc1, h3, wb1.y);
            }
            __syncthreads();
        }

        // gh -> SMEM (rows 4rg..4rg+3)
        {
            float2 f0 = unpack2(acc0), f1 = unpack2(acc1);
            gh_s[(4 * rg + 0) * 66 + b] = f0.x;
            gh_s[(4 * rg + 1) * 66 + b] = f0.y;
            gh_s[(4 * rg + 2) * 66 + b] = f1.x;
            gh_s[(4 * rg + 3) * 66 + b] = f1.y;
        }
        __syncthreads();

        // Gate epilogue + h update
#pragma unroll
        for (int t = 0; t < 2; t++) {
            if (t < e_n) {
                int jj = (tid + t * THR) >> 6;
                float ghr = gh_s[(jj * 3 + 0) * 66 + e_b[t]] + e_bhr[t];
                float ghz = gh_s[(jj * 3 + 1) * 66 + e_b[t]] + e_bhz[t];
                float ghn = gh_s[(jj * 3 + 2) * 66 + e_b[t]] + e_bhn[t];
                float r = 1.f / (1.f + expf(-(p_gir[t] + ghr)));
                float z = 1.f / (1.f + expf(-(p_giz[t] + ghz)));
                float n = tanhf(p_gin[t] + r * ghn);
                ho[(size_t)e_b[t] * D_H + e_j[t]] = (1.f - z) * n + z * p_hp[t];
            }
        }

        // Grid barrier
        __syncthreads();
        if (tid == 0) {
            __threadfence();
            unsigned a = atomicAdd(&g_cnt, 1u);
            if (a == (unsigned)((s + 1) * GRID - 1)) {
                g_gen = (unsigned)(s + 1);
            } else {
                while (g_gen < (unsigned)(s + 1)) { }
            }
        }
        __syncthreads();
    }
}

// ---------------------------------------------------------------------------
// Kernel C: FC (N=64 full per CTA) + fused log_softmax over the 64 outputs.
// ---------------------------------------------------------------------------
__global__ void k_fc_lsm(const float* __restrict__ fc_w,
                         const float* __restrict__ fc_b,
                         float* __restrict__ out) {
    __shared__ float h_s[32][33];
    __shared__ float w_s[32][65];
    __shared__ float ls[32][65];
    __shared__ float rowred[32];

    const int m0  = blockIdx.x * 32;
    const int tid = threadIdx.x;    // 256
    const int to  = tid & 15;
    const int tm  = tid >> 4;

    float acc[2][4];
#pragma unroll
    for (int a = 0; a < 2; a++)
#pragma unroll
        for (int q = 0; q < 4; q++) acc[a][q] = 0.f;

    for (int k0 = 0; k0 < D_H; k0 += 32) {
#pragma unroll
        for (int i = tid; i < 1024; i += 256) {
            int mm = i >> 5, kk = i & 31;
            h_s[kk][mm] = g_hs[(size_t)(m0 + mm) * D_H + k0 + kk];
        }
#pragma unroll
        for (int i = tid; i < 2048; i += 256) {
            int o = i >> 5, kk = i & 31;
            w_s[kk][o] = fc_w[(size_t)o * D_H + k0 + kk];
        }
        __syncthreads();

#pragma unroll
        for (int kk = 0; kk < 32; kk++) {
            float a0 = h_s[kk][tm];
            float a1 = h_s[kk][tm + 16];
#pragma unroll
            for (int q = 0; q < 4; q++) {
                float w = w_s[kk][to + 16 * q];
                acc[0][q] += a0 * w;
                acc[1][q] += a1 * w;
            }
        }
        __syncthreads();
    }

#pragma unroll
    for (int mi = 0; mi < 2; mi++)
#pragma unroll
        for (int q = 0; q < 4; q++)
            ls[tm + 16 * mi][to + 16 * q] = acc[mi][q] + fc_b[to + 16 * q];
    __syncthreads();

    if (tid < 32) {
        float mx = -1e30f;
#pragma unroll 8
        for (int o = 0; o < 64; o++) mx = fmaxf(mx, ls[tid][o]);
        float ssum = 0.f;
#pragma unroll 8
        for (int o = 0; o < 64; o++) ssum += expf(ls[tid][o] - mx);
        rowred[tid] = mx + logf(ssum);
    }
    __syncthreads();

    for (int i = tid; i < 32 * 64; i += 256) {
        int mm = i >> 6, o = i & 63;
        int m = m0 + mm;
        int bb = m & 63, sIdx = m >> 6;
        out[((size_t)bb * SS + sIdx) * D_OUT + o] = ls[mm][o] - rowred[mm];
    }
}

// ---------------------------------------------------------------------------
// Launch: inputs in setup_inputs order:
//   0:x(int32) 1:emb 2:w_ih 3:w_hh 4:b_ih 5:b_hh 6:fc_w 7:fc_b
// ---------------------------------------------------------------------------
extern "C" void kernel_launch(void* const* d_in, const int* in_sizes, int n_in,
                              void* d_out, int out_size) {
    const int*   x    = (const int*)  d_in[0];
    const float* emb  = (const float*)d_in[1];
    const float* w_ih = (const float*)d_in[2];
    const float* w_hh = (const float*)d_in[3];
    const float* b_ih = (const float*)d_in[4];
    const float* b_hh = (const float*)d_in[5];
    const float* fc_w = (const float*)d_in[6];
    const float* fc_b = (const float*)d_in[7];
    float* out = (float*)d_out;

    const int smem_bytes = (24576 + 2 * 8448 + 24 * 66) * (int)sizeof(float);

    static bool attr_set = false;
    if (!attr_set) {
        cudaFuncSetAttribute(k_gru_persist,
                             cudaFuncAttributeMaxDynamicSharedMemorySize,
                             smem_bytes);
        attr_set = true;
    }

    // Reset grid-barrier state (part of the captured graph -> every replay)
    k_reset<<<1, 1>>>();

    // A: embedding + input projection, [16384 x 3072]
    k_embed_gi<<<dim3(G3H / 128, M_TOT / 128), 256>>>(x, emb, w_ih, b_ih);

    // B: persistent GRU over all 256 steps
    k_gru_persist<<<GRID, THR, smem_bytes>>>(w_hh, b_hh);

    // C: FC + log_softmax
    k_fc_lsm<<<M_TOT / 32, 256>>>(fc_w, fc_b, out);
}

// round 7
// speedup vs baseline: 1.1122x; 1.1122x over previous
#include <cuda_runtime.h>
#include <cuda_bf16.h>
#include <math.h>

// Problem constants
#define VOCAB 32000
#define D_IN  512
#define D_H   1024
#define D_OUT 64
#define BB    64
#define SS    256
#define M_TOT (BB * SS)          // 16384 rows, m = s*64 + b
#define G3H   (3 * D_H)          // 3072
#define GRID  128                // persistent CTAs (1 per SM)
#define THR   512                // threads in persistent kernel (4 warps/SMSP)

// Scratch (device globals — no allocation allowed)
__device__ float g_gi[(size_t)M_TOT * G3H];   // [S][B][3H]  192 MB
__device__ float g_hs[(size_t)M_TOT * D_H];   // [S][B][H]    64 MB
__device__ float g_hzero[BB * D_H];           // stays zero (never written)

// Grid-barrier state (reset each launch by k_reset)
__device__ unsigned g_cnt;
__device__ volatile unsigned g_gen;

__global__ void k_reset() { g_cnt = 0; g_gen = 0; }

// ---- packed fp32x2 helpers (sm_103a FFMA2: PTX-only, exact fp32 per half) ----
__device__ __forceinline__ void fma2(unsigned long long& d,
                                     unsigned long long a,
                                     unsigned long long b) {
    asm("fma.rn.f32x2 %0, %1, %2, %0;" : "+l"(d) : "l"(a), "l"(b));
}
__device__ __forceinline__ unsigned long long pack_dup(float x) {
    unsigned long long r;
    asm("mov.b64 %0, {%1, %1};" : "=l"(r) : "f"(x));
    return r;
}
__device__ __forceinline__ float2 unpack2(unsigned long long v) {
    float2 f;
    asm("mov.b64 {%0, %1}, %2;" : "=f"(f.x), "=f"(f.y) : "l"(v));
    return f;
}

// ---------------------------------------------------------------------------
// Kernel A: fused embedding gather + input projection GEMM (f32x2 inner loop)
//   gi[m][n] = sum_k emb[tok(m)][k] * w_ih[n][k] + b_ih[n]
// ---------------------------------------------------------------------------
__global__ void k_embed_gi(const int* __restrict__ x,
                           const float* __restrict__ emb,
                           const float* __restrict__ w_ih,
                           const float* __restrict__ b_ih) {
    __shared__ __align__(16) float As[16][136];
    __shared__ __align__(16) float Ws[16][136];
    __shared__ int tok[128];

    const int m0 = blockIdx.y * 128;
    const int n0 = blockIdx.x * 128;
    const int tid = threadIdx.x;
    const int tx = tid & 15;
    const int ty = tid >> 4;

    if (tid < 128) {
        int m = m0 + tid;
        tok[tid] = x[(m & 63) * SS + (m >> 6)];
    }
    __syncthreads();

    unsigned long long acc2[8][4];
#pragma unroll
    for (int i = 0; i < 8; i++)
#pragma unroll
        for (int j = 0; j < 4; j++) acc2[i][j] = 0ull;

    for (int k0 = 0; k0 < D_IN; k0 += 16) {
#pragma unroll
        for (int i = tid; i < 2048; i += 256) {
            int mm = i >> 4, kk = i & 15;
            As[kk][mm] = emb[(size_t)tok[mm] * D_IN + k0 + kk];
        }
#pragma unroll
        for (int i = tid; i < 2048; i += 256) {
            int nn = i >> 4, kk = i & 15;
            Ws[kk][nn] = w_ih[(size_t)(n0 + nn) * D_IN + k0 + kk];
        }
        __syncthreads();

#pragma unroll
        for (int kk = 0; kk < 16; kk++) {
            float a[8];
            *(float4*)&a[0] = *(const float4*)&As[kk][ty * 8];
            *(float4*)&a[4] = *(const float4*)&As[kk][ty * 8 + 4];
            ulonglong2 w01 = *(const ulonglong2*)&Ws[kk][tx * 8];
            ulonglong2 w23 = *(const ulonglong2*)&Ws[kk][tx * 8 + 4];
#pragma unroll
            for (int i = 0; i < 8; i++) {
                unsigned long long ad = pack_dup(a[i]);
                fma2(acc2[i][0], ad, w01.x);
                fma2(acc2[i][1], ad, w01.y);
                fma2(acc2[i][2], ad, w23.x);
                fma2(acc2[i][3], ad, w23.y);
            }
        }
        __syncthreads();
    }

    float bias[8];
#pragma unroll
    for (int j = 0; j < 8; j++) bias[j] = b_ih[n0 + tx * 8 + j];

#pragma unroll
    for (int i = 0; i < 8; i++) {
        size_t row = (size_t)(m0 + ty * 8 + i) * G3H + n0 + tx * 8;
        float2 c0 = unpack2(acc2[i][0]);
        float2 c1 = unpack2(acc2[i][1]);
        float2 c2 = unpack2(acc2[i][2]);
        float2 c3 = unpack2(acc2[i][3]);
        float4 v0 = make_float4(c0.x + bias[0], c0.y + bias[1],
                                c1.x + bias[2], c1.y + bias[3]);
        float4 v1 = make_float4(c2.x + bias[4], c2.y + bias[5],
                                c3.x + bias[6], c3.y + bias[7]);
        *(float4*)&g_gi[row]     = v0;
        *(float4*)&g_gi[row + 4] = v1;
    }
}

// ---------------------------------------------------------------------------
// Kernel B: PERSISTENT GRU — all 256 steps in one kernel.
//   128 CTAs x 512 threads (4 warps/SMSP). CTA bid owns j in [bid*8, bid*8+8).
//   Thread map: b = tid&63, jj = tid>>6  -> one (b, j) per thread. Gates r,z
//   paired as f32x2 (w rows interleaved per-k in SMEM), n scalar FFMA.
//   w slice (96 KB) resident in SMEM all sequence. h streamed per step in
//   double-buffered 128-k chunks, [b][k] layout (no transpose, stride 132).
//   Epilogue fully in-register per thread. Grid barrier between steps.
// ---------------------------------------------------------------------------
__global__ void __launch_bounds__(THR, 1)
k_gru_persist(const float* __restrict__ w_hh,
              const float* __restrict__ b_hh) {
    extern __shared__ float sm[];
    float* wrz = sm;                 // [8 jj][1024 k][2 (r,z)]  = 16384 f, 64 KB
    float* wn  = sm + 16384;         // [8 jj][1024 k]           =  8192 f, 32 KB
    float* h_s = sm + 24576;         // [2 bufs][64 b][132]      = 16896 f, 66 KB

    const int tid = threadIdx.x;     // 512
    const int bid = blockIdx.x;      // 128
    const int j0  = bid * 8;
    const int b   = tid & 63;
    const int jj  = tid >> 6;        // 0..7
    const int j   = j0 + jj;

    // One-time: pack w_hh slice into SMEM.
    //   wrz[(jj*1024 + k)*2 + p] = w_hh[(p*D_H + j0+jj)*D_H + k]  (p: 0=r,1=z)
    //   wn [ jj*1024 + k ]       = w_hh[(2*D_H + j0+jj)*D_H + k]
    for (int idx = tid; idx < 16384; idx += THR) {
        int p = idx & 1, k = (idx >> 1) & 1023, jl = idx >> 11;
        wrz[idx] = w_hh[(size_t)(p * D_H + j0 + jl) * D_H + k];
    }
    for (int idx = tid; idx < 8192; idx += THR) {
        int k = idx & 1023, jl = idx >> 10;
        wn[idx] = w_hh[(size_t)(2 * D_H + j0 + jl) * D_H + k];
    }
    const float bhr = b_hh[j];
    const float bhz = b_hh[D_H + j];
    const float bhn = b_hh[2 * D_H + j];
    __syncthreads();

    for (int s = 0; s < SS; s++) {
        const float* hp = (s == 0) ? g_hzero : (g_hs + (size_t)(s - 1) * BB * D_H);
        float* ho = g_hs + (size_t)s * BB * D_H;

        // Prefetch epilogue operands (hidden under the GEMM)
        const float* gi = g_gi + ((size_t)s * BB + b) * G3H;
        const float gir = gi[j];
        const float giz = gi[D_H + j];
        const float gin = gi[2 * D_H + j];
        const float hpv = hp[(size_t)b * D_H + j];

        unsigned long long acc_rz = 0ull;
        float acc_n = 0.f;

        // Load chunk 0: [64 b][128 k] -> h_s, coalesced, no transpose
#pragma unroll
        for (int idx = tid; idx < 2048; idx += THR) {
            int bl = idx >> 5, kq = idx & 31;
            *(float4*)&h_s[bl * 132 + kq * 4] =
                *(const float4*)&hp[(size_t)bl * D_H + kq * 4];
        }
        __syncthreads();

        for (int c = 0; c < 8; c++) {
            const int buf = c & 1;
            if (c < 7) {  // prefetch next chunk into the other buffer
                float* hd = h_s + (buf ^ 1) * 8448;
#pragma unroll
                for (int idx = tid; idx < 2048; idx += THR) {
                    int bl = idx >> 5, kq = idx & 31;
                    *(float4*)&hd[bl * 132 + kq * 4] =
                        *(const float4*)&hp[(size_t)bl * D_H + (c + 1) * 128 + kq * 4];
                }
            }
            const float* hb  = h_s + buf * 8448 + b * 132;
            const float* wz2 = wrz + (jj * 1024 + c * 128) * 2;  // r,z interleaved
            const float* wn1 = wn + jj * 1024 + c * 128;
#pragma unroll 8
            for (int kk = 0; kk < 128; kk += 4) {
                float4 hv = *(const float4*)&hb[kk];
                ulonglong2 wa = *(const ulonglong2*)&wz2[kk * 2];      // k, k+1
                ulonglong2 wb = *(const ulonglong2*)&wz2[kk * 2 + 4];  // k+2, k+3
                float4 wnv = *(const float4*)&wn1[kk];
                fma2(acc_rz, pack_dup(hv.x), wa.x);
                fma2(acc_rz, pack_dup(hv.y), wa.y);
                fma2(acc_rz, pack_dup(hv.z), wb.x);
                fma2(acc_rz, pack_dup(hv.w), wb.y);
                acc_n += hv.x * wnv.x;
                acc_n += hv.y * wnv.y;
                acc_n += hv.z * wnv.z;
                acc_n += hv.w * wnv.w;
            }
            __syncthreads();
        }

        // Gate epilogue + h update (fully per-thread)
        {
            float2 rz = unpack2(acc_rz);
            float r = 1.f / (1.f + expf(-(gir + rz.x + bhr)));
            float z = 1.f / (1.f + expf(-(giz + rz.y + bhz)));
            float n = tanhf(gin + r * (acc_n + bhn));
            ho[(size_t)b * D_H + j] = (1.f - z) * n + z * hpv;
        }

        // Make this thread's h store globally visible, then grid barrier
        __threadfence();
        __syncthreads();
        if (tid == 0) {
            unsigned a = atomicAdd(&g_cnt, 1u);
            if (a == (unsigned)((s + 1) * GRID - 1)) {
                g_gen = (unsigned)(s + 1);
            } else {
                while (g_gen < (unsigned)(s + 1)) { }
            }
        }
        __syncthreads();
    }
}

// ---------------------------------------------------------------------------
// Kernel C: FC (N=64 full per CTA) + fused log_softmax over the 64 outputs.
// ---------------------------------------------------------------------------
__global__ void k_fc_lsm(const float* __restrict__ fc_w,
                         const float* __restrict__ fc_b,
                         float* __restrict__ out) {
    __shared__ float h_s[32][33];
    __shared__ float w_s[32][65];
    __shared__ float ls[32][65];
    __shared__ float rowred[32];

    const int m0  = blockIdx.x * 32;
    const int tid = threadIdx.x;    // 256
    const int to  = tid & 15;
    const int tm  = tid >> 4;

    float acc[2][4];
#pragma unroll
    for (int a = 0; a < 2; a++)
#pragma unroll
        for (int q = 0; q < 4; q++) acc[a][q] = 0.f;

    for (int k0 = 0; k0 < D_H; k0 += 32) {
#pragma unroll
        for (int i = tid; i < 1024; i += 256) {
            int mm = i >> 5, kk = i & 31;
            h_s[kk][mm] = g_hs[(size_t)(m0 + mm) * D_H + k0 + kk];
        }
#pragma unroll
        for (int i = tid; i < 2048; i += 256) {
            int o = i >> 5, kk = i & 31;
            w_s[kk][o] = fc_w[(size_t)o * D_H + k0 + kk];
        }
        __syncthreads();

#pragma unroll
        for (int kk = 0; kk < 32; kk++) {
            float a0 = h_s[kk][tm];
            float a1 = h_s[kk][tm + 16];
#pragma unroll
            for (int q = 0; q < 4; q++) {
                float w = w_s[kk][to + 16 * q];
                acc[0][q] += a0 * w;
                acc[1][q] += a1 * w;
            }
        }
        __syncthreads();
    }

#pragma unroll
    for (int mi = 0; mi < 2; mi++)
#pragma unroll
        for (int q = 0; q < 4; q++)
            ls[tm + 16 * mi][to + 16 * q] = acc[mi][q] + fc_b[to + 16 * q];
    __syncthreads();

    if (tid < 32) {
        float mx = -1e30f;
#pragma unroll 8
        for (int o = 0; o < 64; o++) mx = fmaxf(mx, ls[tid][o]);
        float ssum = 0.f;
#pragma unroll 8
        for (int o = 0; o < 64; o++) ssum += expf(ls[tid][o] - mx);
        rowred[tid] = mx + logf(ssum);
    }
    __syncthreads();

    for (int i = tid; i < 32 * 64; i += 256) {
        int mm = i >> 6, o = i & 63;
        int m = m0 + mm;
        int bb = m & 63, sIdx = m >> 6;
        out[((size_t)bb * SS + sIdx) * D_OUT + o] = ls[mm][o] - rowred[mm];
    }
}

// ---------------------------------------------------------------------------
// Launch: inputs in setup_inputs order:
//   0:x(int32) 1:emb 2:w_ih 3:w_hh 4:b_ih 5:b_hh 6:fc_w 7:fc_b
// ---------------------------------------------------------------------------
extern "C" void kernel_launch(void* const* d_in, const int* in_sizes, int n_in,
                              void* d_out, int out_size) {
    const int*   x    = (const int*)  d_in[0];
    const float* emb  = (const float*)d_in[1];
    const float* w_ih = (const float*)d_in[2];
    const float* w_hh = (const float*)d_in[3];
    const float* b_ih = (const float*)d_in[4];
    const float* b_hh = (const float*)d_in[5];
    const float* fc_w = (const float*)d_in[6];
    const float* fc_b = (const float*)d_in[7];
    float* out = (float*)d_out;

    const int smem_bytes = (24576 + 2 * 8448) * (int)sizeof(float);  // ~162 KB

    static bool attr_set = false;
    if (!attr_set) {
        cudaFuncSetAttribute(k_gru_persist,
                             cudaFuncAttributeMaxDynamicSharedMemorySize,
                             smem_bytes);
        attr_set = true;
    }

    // Reset grid-barrier state (part of the captured graph -> every replay)
    k_reset<<<1, 1>>>();

    // A: embedding + input projection, [16384 x 3072]
    k_embed_gi<<<dim3(G3H / 128, M_TOT / 128), 256>>>(x, emb, w_ih, b_ih);

    // B: persistent GRU over all 256 steps
    k_gru_persist<<<GRID, THR, smem_bytes>>>(w_hh, b_hh);

    // C: FC + log_softmax
    k_fc_lsm<<<M_TOT / 32, 256>>>(fc_w, fc_b, out);
}